// round 3
// baseline (speedup 1.0000x reference)
#include <cuda_runtime.h>

// ---------------- problem constants ----------------
#define B_    8
#define E_    64
#define CIN_  128
#define C_    128
#define PRE_  128
#define SPA_  (E_*E_)          // 4096 spatial
#define BCE_  (B_*C_*E_)       // 65536
#define BSPA_ (B_*SPA_)        // 32768

// ---------------- scratch (__device__ globals: allocation-free) ----------------
__device__ float g_xf  [BCE_];            // [b][c][m]
__device__ float g_yf  [BCE_];            // [b][c][n]
__device__ float g_xlin[BCE_];            // [b][i][m]
__device__ float g_ylin[BCE_];            // [b][i][n]
__device__ float g_logist[BSPA_];         // [b][m][n]
__device__ float g_gmat [BSPA_];          // [b][m][n]
__device__ float g_ptd[32];
__device__ float g_etd[16];
__device__ float g_xret[B_*C_*SPA_];      // [b][c][e][m]  16 MB
__device__ float g_yret[B_*C_*SPA_];      // [b][c][e][n]  16 MB
__device__ float g_h   [B_*C_*SPA_];      // conv1 output  16 MB
__device__ float g_w1t [384*128];         // conv1_w transposed [k][o]
__device__ float g_w2t [128*9*128];       // conv2_w transposed [c*9+kyx][o]

__device__ __forceinline__ float leaky(float v) { return v >= 0.f ? v : 0.1f * v; }

// ---------------- K0: type-dot precompute + weight transposes ----------------
__global__ void k_prep(const float* __restrict__ path_table, const float* __restrict__ pconv_w,
                       const float* __restrict__ edge_table, const float* __restrict__ econv_w,
                       const float* __restrict__ conv1_w,    const float* __restrict__ conv2_w) {
    int tid = blockIdx.x * blockDim.x + threadIdx.x;
    int stride = gridDim.x * blockDim.x;
    if (blockIdx.x == 0) {
        if (threadIdx.x < 20) {
            float s = 0.f;
            #pragma unroll
            for (int d = 0; d < 32; d++) s += path_table[threadIdx.x*32 + d] * pconv_w[d];
            g_ptd[threadIdx.x] = leaky(s);
        }
        if (threadIdx.x >= 32 && threadIdx.x < 42) {
            int t = threadIdx.x - 32;
            float s = 0.f;
            #pragma unroll
            for (int d = 0; d < 32; d++) s += edge_table[t*32 + d] * econv_w[d];
            g_etd[t] = leaky(s);
        }
    }
    for (int idx = tid; idx < 384*128; idx += stride) {
        int k = idx >> 7, o = idx & 127;
        g_w1t[idx] = conv1_w[o*384 + k];
    }
    for (int idx = tid; idx < 128*9*128; idx += stride) {
        int c9 = idx >> 7, o = idx & 127;
        g_w2t[idx] = conv2_w[o*1152 + c9];
    }
}

// ---------------- K1: x_f/y_f and x_lin/y_lin (128x128 @ 128x64 per b) ----------------
__global__ void k_feat(const float* __restrict__ x, const float* __restrict__ y,
                       const float* __restrict__ xc1_w, const float* __restrict__ yc1_w,
                       const float* __restrict__ xlin_w, const float* __restrict__ ylin_w) {
    int b = blockIdx.x;
    bool isx = (blockIdx.y == 0);
    const float* X  = (isx ? x : y) + b * 8192;
    const float* W1 = isx ? xc1_w : yc1_w;
    const float* Wl = isx ? xlin_w : ylin_w;
    float* F = (isx ? g_xf : g_yf) + b * 8192;
    float* L = (isx ? g_xlin : g_ylin) + b * 8192;

    __shared__ __align__(16) float Xs[128*64];
    for (int idx = threadIdx.x; idx < 8192; idx += 256) Xs[idx] = X[idx];
    __syncthreads();

    int m = threadIdx.x & 63, gr = threadIdx.x >> 6;
    for (int c = gr; c < 128; c += 4) {
        float acc = 0.f;
        const float* w = &W1[c*128];
        #pragma unroll 8
        for (int i = 0; i < 128; i++) acc = fmaf(w[i], Xs[i*64 + m], acc);
        F[c*64 + m] = acc;
    }
    for (int i = gr; i < 128; i += 4) {
        float acc = 0.f;
        const float* w = &Wl[i*128];
        #pragma unroll 8
        for (int j = 0; j < 128; j++) acc = fmaf(w[j], Xs[j*64 + m], acc);
        L[i*64 + m] = acc;   // g_xlin[b][i][m]
    }
}

// ---------------- K2: x_self, y_other, logist ----------------
__global__ void k_selflog(const float* __restrict__ xc2_w, const float* __restrict__ xc2_b,
                          const float* __restrict__ yc2_w, const float* __restrict__ yc2_b) {
    int b = blockIdx.x, t = threadIdx.x;
    __shared__ float xs[64], ys[64];
    if (t < 64) {
        float a = 0.f;
        #pragma unroll 8
        for (int c = 0; c < 128; c++) a = fmaf(xc2_w[c], g_xf[(b*128 + c)*64 + t], a);
        xs[t] = a + xc2_b[0];
    } else {
        int n = t - 64;
        float a = 0.f;
        #pragma unroll 8
        for (int c = 0; c < 128; c++) a = fmaf(yc2_w[c], g_yf[(b*128 + c)*64 + n], a);
        ys[n] = a + yc2_b[0];
    }
    __syncthreads();
    for (int idx = t; idx < 4096; idx += 128) {
        int i = idx >> 6, j = idx & 63;
        g_logist[b*4096 + idx] = leaky(xs[j] + ys[i]);   // logist[b,i,j]=leaky(x_self[j]+y_other[i])
    }
}

// ---------------- K3: per-(b,e) path attention + x_ret/y_ret ----------------
// dyn smem: P[64][65] | Ys[128][65] | Xs[128][65]
#define SMEM_PATH ((64*65 + 128*65 + 128*65) * 4)
__global__ void k_path(const float* __restrict__ p_bias, const int* __restrict__ path_mat) {
    extern __shared__ float sm[];
    float* Ps = sm;
    float* Ys = Ps + 64*65;
    float* Xs = Ys + 128*65;
    __shared__ float ptd_s[32];
    __shared__ float red[8];
    __shared__ float rinv[64], cinv[64];

    int tid = threadIdx.x;
    int be = blockIdx.x, b = be >> 6, e = be & 63;
    if (tid < 32) ptd_s[tid] = g_ptd[tid];

    for (int idx = tid; idx < 8192; idx += 256) {
        int c = idx >> 6, n = idx & 63;
        Ys[c*65 + n] = g_yf[b*8192 + idx];
        Xs[c*65 + n] = g_xf[b*8192 + idx];
    }
    __syncthreads();

    // local = logist[b,m,n] + ptd[path_mat[b,e,m,n]] + p_bias[b,e,m,n]; track block max
    const int base = be << 12;
    float lm = -1e30f;
    for (int idx = tid; idx < 4096; idx += 256) {
        int m = idx >> 6, n = idx & 63;
        float v = g_logist[b*4096 + idx] + ptd_s[path_mat[base + idx]] + p_bias[base + idx];
        Ps[m*65 + n] = v;
        lm = fmaxf(lm, v);
    }
    #pragma unroll
    for (int off = 16; off; off >>= 1) lm = fmaxf(lm, __shfl_xor_sync(0xffffffffu, lm, off));
    if ((tid & 31) == 0) red[tid >> 5] = lm;
    __syncthreads();
    float T = red[0];
    #pragma unroll
    for (int w = 1; w < 8; w++) T = fmaxf(T, red[w]);

    // one exp serves both softmaxes exactly (constant T cancels in each normalization)
    for (int idx = tid; idx < 4096; idx += 256) {
        int m = idx >> 6, n = idx & 63;
        Ps[m*65 + n] = __expf(Ps[m*65 + n] - T);
    }
    __syncthreads();
    if (tid < 64) {
        float s = 0.f;
        #pragma unroll 8
        for (int n = 0; n < 64; n++) s += Ps[tid*65 + n];
        rinv[tid] = 1.f / s;
    } else if (tid < 128) {
        int n = tid - 64;
        float s = 0.f;
        #pragma unroll 8
        for (int m = 0; m < 64; m++) s += Ps[m*65 + n];
        cinv[n] = 1.f / s;
    }
    __syncthreads();

    // x_ret[b,c,e,m] = leaky(rinv[m]*sum_n P[m,n]*Yf[c,n] + Xf[c,m])
    {
        int mg = tid & 7, cg = tid >> 3;
        int m0 = mg * 8, c0 = cg * 4;
        float acc[4][8];
        #pragma unroll
        for (int q = 0; q < 4; q++)
            #pragma unroll
            for (int k = 0; k < 8; k++) acc[q][k] = 0.f;
        #pragma unroll 4
        for (int n = 0; n < 64; n++) {
            float pv[8];
            #pragma unroll
            for (int k = 0; k < 8; k++) pv[k] = Ps[(m0 + k)*65 + n];
            #pragma unroll
            for (int q = 0; q < 4; q++) {
                float yv = Ys[(c0 + q)*65 + n];
                #pragma unroll
                for (int k = 0; k < 8; k++) acc[q][k] = fmaf(pv[k], yv, acc[q][k]);
            }
        }
        #pragma unroll
        for (int q = 0; q < 4; q++) {
            int c = c0 + q;
            float o[8];
            #pragma unroll
            for (int k = 0; k < 8; k++)
                o[k] = leaky(acc[q][k]*rinv[m0 + k] + Xs[c*65 + m0 + k]);
            float4* dst = (float4*)&g_xret[(((b*128) + c)*64 + e)*64 + m0];
            dst[0] = make_float4(o[0], o[1], o[2], o[3]);
            dst[1] = make_float4(o[4], o[5], o[6], o[7]);
        }
    }
    // y_ret[b,c,e,n] = leaky(cinv[n]*sum_m P[m,n]*Xf[c,m] + Yf[c,n])
    {
        int ng = tid & 7, cg = tid >> 3;
        int n0 = ng * 8, c0 = cg * 4;
        float acc[4][8];
        #pragma unroll
        for (int q = 0; q < 4; q++)
            #pragma unroll
            for (int k = 0; k < 8; k++) acc[q][k] = 0.f;
        #pragma unroll 4
        for (int m = 0; m < 64; m++) {
            float pv[8];
            #pragma unroll
            for (int k = 0; k < 8; k++) pv[k] = Ps[m*65 + n0 + k];
            #pragma unroll
            for (int q = 0; q < 4; q++) {
                float xv = Xs[(c0 + q)*65 + m];
                #pragma unroll
                for (int k = 0; k < 8; k++) acc[q][k] = fmaf(pv[k], xv, acc[q][k]);
            }
        }
        #pragma unroll
        for (int q = 0; q < 4; q++) {
            int c = c0 + q;
            float o[8];
            #pragma unroll
            for (int k = 0; k < 8; k++)
                o[k] = leaky(acc[q][k]*cinv[n0 + k] + Ys[c*65 + n0 + k]);
            float4* dst = (float4*)&g_yret[(((b*128) + c)*64 + e)*64 + n0];
            dst[0] = make_float4(o[0], o[1], o[2], o[3]);
            dst[1] = make_float4(o[4], o[5], o[6], o[7]);
        }
    }
}

// ---------------- K4: fused men-concat + 1x1 conv + leaky ----------------
// grid (s_tile=64, o_tile=2, b=8); block 256 = 16 sg x 16 og; micro-tile 4o x 4s
__global__ void k_conv1(const float* __restrict__ pre_out, const float* __restrict__ conv1_b) {
    __shared__ __align__(16) float Ins[32*64];
    __shared__ __align__(16) float Wts[32*64];
    int tid = threadIdx.x;
    int sg = tid & 15, og = tid >> 4;
    int s0 = blockIdx.x * 64, o0 = blockIdx.y * 64, b = blockIdx.z;

    float acc[4][4];
    #pragma unroll
    for (int i = 0; i < 4; i++)
        #pragma unroll
        for (int j = 0; j < 4; j++) acc[i][j] = 0.f;

    for (int kb = 0; kb < 384; kb += 32) {
        __syncthreads();
        const float* src = (kb < 128) ? &g_xret[(b*128 + kb)*4096 + s0]
                         : (kb < 256) ? &g_yret[(b*128 + (kb - 128))*4096 + s0]
                                      : &pre_out[(size_t)(b*128 + (kb - 256))*4096 + s0];
        for (int l = tid; l < 2048; l += 256) {
            int kk = l >> 6, s = l & 63;
            Ins[l] = src[kk*4096 + s];
        }
        for (int l = tid; l < 2048; l += 256) {
            int kk = l >> 6, oo = l & 63;
            Wts[l] = g_w1t[(kb + kk)*128 + o0 + oo];
        }
        __syncthreads();
        #pragma unroll 8
        for (int kk = 0; kk < 32; kk++) {
            float4 iv = *(const float4*)&Ins[kk*64 + sg*4];
            float4 wv = *(const float4*)&Wts[kk*64 + og*4];
            float in4[4] = {iv.x, iv.y, iv.z, iv.w};
            float w4[4]  = {wv.x, wv.y, wv.z, wv.w};
            #pragma unroll
            for (int oo = 0; oo < 4; oo++)
                #pragma unroll
                for (int ss = 0; ss < 4; ss++)
                    acc[oo][ss] = fmaf(w4[oo], in4[ss], acc[oo][ss]);
        }
    }
    #pragma unroll
    for (int oo = 0; oo < 4; oo++) {
        int o = o0 + og*4 + oo;
        float bv = conv1_b[o];
        float4 r;
        r.x = leaky(acc[oo][0] + bv);
        r.y = leaky(acc[oo][1] + bv);
        r.z = leaky(acc[oo][2] + bv);
        r.w = leaky(acc[oo][3] + bv);
        *(float4*)&g_h[(size_t)(b*128 + o)*4096 + s0 + sg*4] = r;
    }
}

// ---------------- K5: 3x3 conv + bias + leaky -> men2rel, fused scores + g assembly ----------------
// grid (i=64, b=8); block 256 = 16 jg x 16 og; micro-tile 8o x 4j; CC=8 channel chunks
__global__ void k_conv2(const float* __restrict__ conv2_b, float* __restrict__ men,
                        const float* __restrict__ score_w, const int* __restrict__ edge_mat,
                        const float* __restrict__ m_bias) {
    const int CC = 8;
    __shared__ __align__(16) float hs[CC*3*68];
    __shared__ __align__(16) float ws[CC*9*128];
    __shared__ float scr[16*64];   // per-og partial score sums, [og][j]
    int tid = threadIdx.x;
    int jg = tid & 15, og = tid >> 4;
    int j0 = jg * 4, o0 = og * 8;
    int i = blockIdx.x, b = blockIdx.y;

    float acc[8][4];
    #pragma unroll
    for (int a = 0; a < 8; a++)
        #pragma unroll
        for (int j = 0; j < 4; j++) acc[a][j] = 0.f;

    for (int cb = 0; cb < 128; cb += CC) {
        __syncthreads();
        for (int l = tid; l < CC*3*66; l += 256) {
            int c = l / 198, r = l % 198;
            int ky = r / 66, jj = r % 66;
            int gi = i + ky - 1, gj = jj - 1;
            float v = 0.f;
            if (gi >= 0 && gi < 64 && gj >= 0 && gj < 64)
                v = g_h[((size_t)(b*128 + cb + c)*64 + gi)*64 + gj];
            hs[(c*3 + ky)*68 + jj] = v;
        }
        for (int l = tid; l < CC*9*128; l += 256)
            ws[l] = g_w2t[cb*9*128 + l];
        __syncthreads();

        #pragma unroll
        for (int c2 = 0; c2 < CC; c2++) {
            #pragma unroll
            for (int ky = 0; ky < 3; ky++) {
                const float* hr = &hs[(c2*3 + ky)*68 + j0];
                float hv[6];
                #pragma unroll
                for (int t = 0; t < 6; t++) hv[t] = hr[t];
                #pragma unroll
                for (int kx = 0; kx < 3; kx++) {
                    const float* wp = &ws[((c2*3 + ky)*3 + kx)*128 + o0];
                    float4 w0 = *(const float4*)wp;
                    float4 w1 = *(const float4*)(wp + 4);
                    float w8[8] = {w0.x, w0.y, w0.z, w0.w, w1.x, w1.y, w1.z, w1.w};
                    #pragma unroll
                    for (int jj = 0; jj < 4; jj++) {
                        float h_ = hv[jj + kx];
                        #pragma unroll
                        for (int oo = 0; oo < 8; oo++)
                            acc[oo][jj] = fmaf(w8[oo], h_, acc[oo][jj]);
                    }
                }
            }
        }
    }
    // epilogue: bias+leaky, write men2rel, accumulate score partials
    float part[4] = {0.f, 0.f, 0.f, 0.f};
    #pragma unroll
    for (int oo = 0; oo < 8; oo++) {
        int o = o0 + oo;
        float bv = conv2_b[o];
        float sw = score_w[o];
        float r0 = leaky(acc[oo][0] + bv);
        float r1 = leaky(acc[oo][1] + bv);
        float r2 = leaky(acc[oo][2] + bv);
        float r3 = leaky(acc[oo][3] + bv);
        part[0] = fmaf(sw, r0, part[0]);
        part[1] = fmaf(sw, r1, part[1]);
        part[2] = fmaf(sw, r2, part[2]);
        part[3] = fmaf(sw, r3, part[3]);
        *(float4*)&men[((size_t)(b*128 + o)*64 + i)*64 + j0] = make_float4(r0, r1, r2, r3);
    }
    #pragma unroll
    for (int jj = 0; jj < 4; jj++) scr[og*64 + j0 + jj] = part[jj];
    __syncthreads();
    if (tid < 64) {
        int j = tid;
        float s = 0.f;
        #pragma unroll
        for (int g = 0; g < 16; g++) s += scr[g*64 + j];
        int idx = b*4096 + i*64 + j;
        g_gmat[idx] = g_logist[idx] + leaky(s) + g_etd[edge_mat[idx]] + m_bias[idx];
    }
}

// ---------------- K7: final softmax-attention + residual ----------------
// dyn smem: P[64][65] | Yl[64][129] | Xl[64][129]
#define SMEM_FINAL ((64*65 + 2*64*129) * 4)
__global__ void k_final(const float* __restrict__ x, const float* __restrict__ y,
                        float* __restrict__ out_x, float* __restrict__ out_y) {
    extern __shared__ float sm[];
    float* Ps = sm;
    float* Yl = Ps + 64*65;
    float* Xl = Yl + 64*129;
    __shared__ float red[8];
    __shared__ float rinv[64], cinv[64];
    int tid = threadIdx.x, b = blockIdx.x;

    float lm = -1e30f;
    for (int idx = tid; idx < 4096; idx += 256) {
        int m = idx >> 6, n = idx & 63;
        float v = g_gmat[b*4096 + idx];
        Ps[m*65 + n] = v;
        lm = fmaxf(lm, v);
    }
    for (int idx = tid; idx < 8192; idx += 256) {
        int i = idx >> 6, k = idx & 63;
        Yl[k*129 + i] = g_ylin[b*8192 + idx];
        Xl[k*129 + i] = g_xlin[b*8192 + idx];
    }
    #pragma unroll
    for (int off = 16; off; off >>= 1) lm = fmaxf(lm, __shfl_xor_sync(0xffffffffu, lm, off));
    if ((tid & 31) == 0) red[tid >> 5] = lm;
    __syncthreads();
    float T = red[0];
    #pragma unroll
    for (int w = 1; w < 8; w++) T = fmaxf(T, red[w]);
    for (int idx = tid; idx < 4096; idx += 256) {
        int m = idx >> 6, n = idx & 63;
        Ps[m*65 + n] = __expf(Ps[m*65 + n] - T);
    }
    __syncthreads();
    if (tid < 64) {
        float s = 0.f;
        #pragma unroll 8
        for (int n = 0; n < 64; n++) s += Ps[tid*65 + n];
        rinv[tid] = 1.f / s;
    } else if (tid < 128) {
        int n = tid - 64;
        float s = 0.f;
        #pragma unroll 8
        for (int m = 0; m < 64; m++) s += Ps[m*65 + n];
        cinv[n] = 1.f / s;
    }
    __syncthreads();

    int m = tid & 63, ig = tid >> 6;
    for (int i = ig; i < 128; i += 4) {
        float a = 0.f;
        #pragma unroll 8
        for (int n = 0; n < 64; n++) a = fmaf(Ps[m*65 + n], Yl[n*129 + i], a);
        out_x[(b*128 + i)*64 + m] = a*rinv[m] + x[(b*128 + i)*64 + m];
    }
    for (int i = ig; i < 128; i += 4) {
        float a = 0.f;
        #pragma unroll 8
        for (int mm = 0; mm < 64; mm++) a = fmaf(Ps[mm*65 + m], Xl[mm*129 + i], a);
        out_y[(b*128 + i)*64 + m] = a*cinv[m] + y[(b*128 + i)*64 + m];
    }
}

// ---------------- launch ----------------
extern "C" void kernel_launch(void* const* d_in, const int* in_sizes, int n_in,
                              void* d_out, int out_size) {
    const float* x          = (const float*)d_in[0];
    const float* y          = (const float*)d_in[1];
    const float* m_bias     = (const float*)d_in[2];
    const int*   edge_mat   = (const int*)  d_in[3];
    const float* p_bias     = (const float*)d_in[4];
    const int*   path_mat   = (const int*)  d_in[5];
    const float* pre_out    = (const float*)d_in[6];
    const float* xc1_w      = (const float*)d_in[7];
    const float* yc1_w      = (const float*)d_in[8];
    const float* xc2_w      = (const float*)d_in[9];
    const float* xc2_b      = (const float*)d_in[10];
    const float* yc2_w      = (const float*)d_in[11];
    const float* yc2_b      = (const float*)d_in[12];
    const float* pconv_w    = (const float*)d_in[13];
    const float* econv_w    = (const float*)d_in[14];
    const float* conv1_w    = (const float*)d_in[15];
    const float* conv1_b    = (const float*)d_in[16];
    const float* conv2_w    = (const float*)d_in[17];
    const float* conv2_b    = (const float*)d_in[18];
    const float* score_w    = (const float*)d_in[19];
    const float* xlin_w     = (const float*)d_in[20];
    const float* ylin_w     = (const float*)d_in[21];
    const float* edge_table = (const float*)d_in[22];
    const float* path_table = (const float*)d_in[23];

    float* out_x = (float*)d_out;                  // [B,CIN,E]
    float* out_y = out_x + B_*CIN_*E_;             // [B,CIN,E]
    float* men   = out_y + B_*CIN_*E_;             // [B,C,E,E]

    cudaFuncSetAttribute(k_path,  cudaFuncAttributeMaxDynamicSharedMemorySize, SMEM_PATH);
    cudaFuncSetAttribute(k_final, cudaFuncAttributeMaxDynamicSharedMemorySize, SMEM_FINAL);

    k_prep<<<64, 256>>>(path_table, pconv_w, edge_table, econv_w, conv1_w, conv2_w);
    k_feat<<<dim3(B_, 2), 256>>>(x, y, xc1_w, yc1_w, xlin_w, ylin_w);
    k_selflog<<<B_, 128>>>(xc2_w, xc2_b, yc2_w, yc2_b);
    k_path<<<B_*E_, 256, SMEM_PATH>>>(p_bias, path_mat);
    k_conv1<<<dim3(64, 2, B_), 256>>>(pre_out, conv1_b);
    k_conv2<<<dim3(64, B_), 256>>>(conv2_b, men, score_w, edge_mat, m_bias);
    k_final<<<B_, 256, SMEM_FINAL>>>(x, y, out_x, out_y);
}

// round 6
// speedup vs baseline: 1.0548x; 1.0548x over previous
#include <cuda_runtime.h>

// ---------------- problem constants ----------------
#define B_    8
#define E_    64
#define CIN_  128
#define C_    128
#define PRE_  128
#define SPA_  (E_*E_)
#define BCE_  (B_*C_*E_)
#define BSPA_ (B_*SPA_)

typedef unsigned long long u64t;

// ---------------- scratch ----------------
__device__ float g_xf  [BCE_];
__device__ float g_yf  [BCE_];
__device__ float g_xlin[BCE_];
__device__ float g_ylin[BCE_];
__device__ float g_logist[BSPA_];
__device__ float g_gmat [BSPA_];
__device__ float g_ptd[32];
__device__ float g_etd[16];
__device__ float g_xret[B_*C_*SPA_];
__device__ float g_yret[B_*C_*SPA_];
__device__ float g_h   [B_*C_*SPA_];
__device__ float g_w1t [384*128];
__device__ float g_w2t [128*9*128];

__device__ __forceinline__ float leaky(float v) { return v >= 0.f ? v : 0.1f * v; }

// f32x2 packed helpers (FFMA2 path: 2x fp32 throughput, exact fp32 rounding)
__device__ __forceinline__ u64t pack2(float lo, float hi) {
    u64t r; asm("mov.b64 %0, {%1, %2};" : "=l"(r) : "f"(lo), "f"(hi)); return r;
}
__device__ __forceinline__ void unpack2(u64t v, float& lo, float& hi) {
    asm("mov.b64 {%0, %1}, %2;" : "=f"(lo), "=f"(hi) : "l"(v));
}
__device__ __forceinline__ void ffma2(u64t& d, u64t a, u64t b) {
    asm("fma.rn.f32x2 %0, %1, %2, %0;" : "+l"(d) : "l"(a), "l"(b));
}

// ---------------- K0: type-dot precompute + weight transposes ----------------
__global__ void k_prep(const float* __restrict__ path_table, const float* __restrict__ pconv_w,
                       const float* __restrict__ edge_table, const float* __restrict__ econv_w,
                       const float* __restrict__ conv1_w,    const float* __restrict__ conv2_w) {
    int tid = blockIdx.x * blockDim.x + threadIdx.x;
    int stride = gridDim.x * blockDim.x;
    if (blockIdx.x == 0) {
        if (threadIdx.x < 20) {
            float s = 0.f;
            #pragma unroll
            for (int d = 0; d < 32; d++) s += path_table[threadIdx.x*32 + d] * pconv_w[d];
            g_ptd[threadIdx.x] = leaky(s);
        }
        if (threadIdx.x >= 32 && threadIdx.x < 42) {
            int t = threadIdx.x - 32;
            float s = 0.f;
            #pragma unroll
            for (int d = 0; d < 32; d++) s += edge_table[t*32 + d] * econv_w[d];
            g_etd[t] = leaky(s);
        }
    }
    for (int idx = tid; idx < 384*128; idx += stride) {
        int k = idx >> 7, o = idx & 127;
        g_w1t[idx] = conv1_w[o*384 + k];
    }
    for (int idx = tid; idx < 128*9*128; idx += stride) {
        int c9 = idx >> 7, o = idx & 127;
        g_w2t[idx] = conv2_w[o*1152 + c9];
    }
}

// ---------------- K1: x_f/y_f and x_lin/y_lin ----------------
__global__ void k_feat(const float* __restrict__ x, const float* __restrict__ y,
                       const float* __restrict__ xc1_w, const float* __restrict__ yc1_w,
                       const float* __restrict__ xlin_w, const float* __restrict__ ylin_w) {
    int b = blockIdx.x;
    bool isx = (blockIdx.y == 0);
    const float* X  = (isx ? x : y) + b * 8192;
    const float* W1 = isx ? xc1_w : yc1_w;
    const float* Wl = isx ? xlin_w : ylin_w;
    float* F = (isx ? g_xf : g_yf) + b * 8192;
    float* L = (isx ? g_xlin : g_ylin) + b * 8192;

    __shared__ __align__(16) float Xs[128*64];
    for (int idx = threadIdx.x; idx < 8192; idx += 256) Xs[idx] = X[idx];
    __syncthreads();

    int m = threadIdx.x & 63, gr = threadIdx.x >> 6;
    for (int c = gr; c < 128; c += 4) {
        float acc = 0.f;
        const float* w = &W1[c*128];
        #pragma unroll 8
        for (int i = 0; i < 128; i++) acc = fmaf(w[i], Xs[i*64 + m], acc);
        F[c*64 + m] = acc;
    }
    for (int i = gr; i < 128; i += 4) {
        float acc = 0.f;
        const float* w = &Wl[i*128];
        #pragma unroll 8
        for (int j = 0; j < 128; j++) acc = fmaf(w[j], Xs[j*64 + m], acc);
        L[i*64 + m] = acc;
    }
}

// ---------------- K2: x_self, y_other, logist ----------------
__global__ void k_selflog(const float* __restrict__ xc2_w, const float* __restrict__ xc2_b,
                          const float* __restrict__ yc2_w, const float* __restrict__ yc2_b) {
    int b = blockIdx.x, t = threadIdx.x;
    __shared__ float xs[64], ys[64];
    if (t < 64) {
        float a = 0.f;
        #pragma unroll 8
        for (int c = 0; c < 128; c++) a = fmaf(xc2_w[c], g_xf[(b*128 + c)*64 + t], a);
        xs[t] = a + xc2_b[0];
    } else {
        int n = t - 64;
        float a = 0.f;
        #pragma unroll 8
        for (int c = 0; c < 128; c++) a = fmaf(yc2_w[c], g_yf[(b*128 + c)*64 + n], a);
        ys[n] = a + yc2_b[0];
    }
    __syncthreads();
    for (int idx = t; idx < 4096; idx += 128) {
        int i = idx >> 6, j = idx & 63;
        g_logist[b*4096 + idx] = leaky(xs[j] + ys[i]);
    }
}

// ---------------- K3: per-(b,e) path attention + x_ret/y_ret ----------------
// dyn smem: Ps[64][68] | PT[64][68] | Ys[128][65] | Xs[128][65]
#define PP 68
#define SMEM_PATH ((2*64*PP + 2*128*65) * 4)
__global__ void k_path(const float* __restrict__ p_bias, const int* __restrict__ path_mat) {
    extern __shared__ __align__(16) float sm[];
    float* Ps = sm;
    float* PT = Ps + 64*PP;
    float* Ys = PT + 64*PP;
    float* Xs = Ys + 128*65;
    __shared__ float ptd_s[32];
    __shared__ float red[8];
    __shared__ float rinv[64], cinv[64];

    int tid = threadIdx.x;
    int be = blockIdx.x, b = be >> 6, e = be & 63;
    if (tid < 32) ptd_s[tid] = g_ptd[tid];

    for (int idx = tid; idx < 8192; idx += 256) {
        int c = idx >> 6, n = idx & 63;
        Ys[c*65 + n] = g_yf[b*8192 + idx];
        Xs[c*65 + n] = g_xf[b*8192 + idx];
    }
    __syncthreads();

    const int base = be << 12;
    float lm = -1e30f;
    for (int idx = tid; idx < 4096; idx += 256) {
        int m = idx >> 6, n = idx & 63;
        float v = g_logist[b*4096 + idx] + ptd_s[path_mat[base + idx]] + p_bias[base + idx];
        Ps[m*PP + n] = v;
        lm = fmaxf(lm, v);
    }
    #pragma unroll
    for (int off = 16; off; off >>= 1) lm = fmaxf(lm, __shfl_xor_sync(0xffffffffu, lm, off));
    if ((tid & 31) == 0) red[tid >> 5] = lm;
    __syncthreads();
    float T = red[0];
    #pragma unroll
    for (int w = 1; w < 8; w++) T = fmaxf(T, red[w]);

    // shared exp serves both softmaxes exactly; write P and P^T
    for (int idx = tid; idx < 4096; idx += 256) {
        int m = idx >> 6, n = idx & 63;
        float v = __expf(Ps[m*PP + n] - T);
        Ps[m*PP + n] = v;
        PT[n*PP + m] = v;
    }
    __syncthreads();
    if (tid < 64) {          // row sums via PT (conflict-free)
        float s = 0.f;
        #pragma unroll 8
        for (int n = 0; n < 64; n++) s += PT[n*PP + tid];
        rinv[tid] = 1.f / s;
    } else if (tid < 128) {  // col sums via Ps (conflict-free)
        int n = tid - 64;
        float s = 0.f;
        #pragma unroll 8
        for (int m = 0; m < 64; m++) s += Ps[m*PP + n];
        cinv[n] = 1.f / s;
    }
    __syncthreads();

    int mg = tid & 7, cg = tid >> 3;
    int m0 = mg * 8, c0 = cg * 4;

    // x_ret[b,c,e,m] = leaky(rinv[m]*sum_n P[m,n]*Yf[c,n] + Xf[c,m])
    {
        u64t acc2[4][4];
        #pragma unroll
        for (int q = 0; q < 4; q++)
            #pragma unroll
            for (int p = 0; p < 4; p++) acc2[q][p] = 0ULL;
        #pragma unroll 4
        for (int n = 0; n < 64; n++) {
            const ulonglong2* pp = (const ulonglong2*)&PT[n*PP + m0];
            ulonglong2 pa = pp[0], pb = pp[1];   // P[m0..m0+7][n] as 4 pairs
            #pragma unroll
            for (int q = 0; q < 4; q++) {
                u64t yb = pack2(Ys[(c0 + q)*65 + n], Ys[(c0 + q)*65 + n]);
                ffma2(acc2[q][0], pa.x, yb);
                ffma2(acc2[q][1], pa.y, yb);
                ffma2(acc2[q][2], pb.x, yb);
                ffma2(acc2[q][3], pb.y, yb);
            }
        }
        #pragma unroll
        for (int q = 0; q < 4; q++) {
            int c = c0 + q;
            float o[8];
            #pragma unroll
            for (int p = 0; p < 4; p++) {
                float lo, hi;
                unpack2(acc2[q][p], lo, hi);
                o[2*p]   = leaky(lo*rinv[m0 + 2*p]   + Xs[c*65 + m0 + 2*p]);
                o[2*p+1] = leaky(hi*rinv[m0 + 2*p+1] + Xs[c*65 + m0 + 2*p+1]);
            }
            float4* dst = (float4*)&g_xret[(((b*128) + c)*64 + e)*64 + m0];
            dst[0] = make_float4(o[0], o[1], o[2], o[3]);
            dst[1] = make_float4(o[4], o[5], o[6], o[7]);
        }
    }
    // y_ret[b,c,e,n] = leaky(cinv[n]*sum_m P[m,n]*Xf[c,m] + Yf[c,n])
    {
        int n0 = m0;
        u64t acc2[4][4];
        #pragma unroll
        for (int q = 0; q < 4; q++)
            #pragma unroll
            for (int p = 0; p < 4; p++) acc2[q][p] = 0ULL;
        #pragma unroll 4
        for (int m = 0; m < 64; m++) {
            const ulonglong2* pp = (const ulonglong2*)&Ps[m*PP + n0];
            ulonglong2 pa = pp[0], pb = pp[1];
            #pragma unroll
            for (int q = 0; q < 4; q++) {
                u64t xb = pack2(Xs[(c0 + q)*65 + m], Xs[(c0 + q)*65 + m]);
                ffma2(acc2[q][0], pa.x, xb);
                ffma2(acc2[q][1], pa.y, xb);
                ffma2(acc2[q][2], pb.x, xb);
                ffma2(acc2[q][3], pb.y, xb);
            }
        }
        #pragma unroll
        for (int q = 0; q < 4; q++) {
            int c = c0 + q;
            float o[8];
            #pragma unroll
            for (int p = 0; p < 4; p++) {
                float lo, hi;
                unpack2(acc2[q][p], lo, hi);
                o[2*p]   = leaky(lo*cinv[n0 + 2*p]   + Ys[c*65 + n0 + 2*p]);
                o[2*p+1] = leaky(hi*cinv[n0 + 2*p+1] + Ys[c*65 + n0 + 2*p+1]);
            }
            float4* dst = (float4*)&g_yret[(((b*128) + c)*64 + e)*64 + n0];
            dst[0] = make_float4(o[0], o[1], o[2], o[3]);
            dst[1] = make_float4(o[4], o[5], o[6], o[7]);
        }
    }
}

// ---------------- K4: fused men-concat + 1x1 conv + leaky (FFMA2) ----------------
// grid (32 s-tiles of 128, 2 o-tiles of 64, b=8); block 256 = 16 sg x 16 og; tile 4o x 8s
__global__ void k_conv1(const float* __restrict__ pre_out, const float* __restrict__ conv1_b) {
    __shared__ __align__(16) float Ins[32*128];
    __shared__ __align__(16) float Wts[32*64];
    int tid = threadIdx.x;
    int sg = tid & 15, og = tid >> 4;
    int S0 = blockIdx.x * 128, O0 = blockIdx.y * 64, b = blockIdx.z;

    u64t acc2[4][4];   // [oo][s-pair]
    #pragma unroll
    for (int i = 0; i < 4; i++)
        #pragma unroll
        for (int j = 0; j < 4; j++) acc2[i][j] = 0ULL;

    for (int kb = 0; kb < 384; kb += 32) {
        __syncthreads();
        const float* src = (kb < 128) ? &g_xret[(b*128 + kb)*4096 + S0]
                         : (kb < 256) ? &g_yret[(b*128 + (kb - 128))*4096 + S0]
                                      : &pre_out[(size_t)(b*128 + (kb - 256))*4096 + S0];
        for (int l = tid; l < 4096; l += 256) {
            int kk = l >> 7, s = l & 127;
            Ins[l] = src[kk*4096 + s];
        }
        for (int l = tid; l < 2048; l += 256) {
            int kk = l >> 6, oo = l & 63;
            Wts[l] = g_w1t[(kb + kk)*128 + O0 + oo];
        }
        __syncthreads();
        #pragma unroll 4
        for (int kk = 0; kk < 32; kk++) {
            const ulonglong2* ip = (const ulonglong2*)&Ins[kk*128 + sg*8];
            ulonglong2 ia = ip[0], ib = ip[1];   // 4 s-pairs
            float4 wv = *(const float4*)&Wts[kk*64 + og*4];
            u64t w0 = pack2(wv.x, wv.x), w1 = pack2(wv.y, wv.y);
            u64t w2 = pack2(wv.z, wv.z), w3 = pack2(wv.w, wv.w);
            ffma2(acc2[0][0], ia.x, w0); ffma2(acc2[0][1], ia.y, w0);
            ffma2(acc2[0][2], ib.x, w0); ffma2(acc2[0][3], ib.y, w0);
            ffma2(acc2[1][0], ia.x, w1); ffma2(acc2[1][1], ia.y, w1);
            ffma2(acc2[1][2], ib.x, w1); ffma2(acc2[1][3], ib.y, w1);
            ffma2(acc2[2][0], ia.x, w2); ffma2(acc2[2][1], ia.y, w2);
            ffma2(acc2[2][2], ib.x, w2); ffma2(acc2[2][3], ib.y, w2);
            ffma2(acc2[3][0], ia.x, w3); ffma2(acc2[3][1], ia.y, w3);
            ffma2(acc2[3][2], ib.x, w3); ffma2(acc2[3][3], ib.y, w3);
        }
    }
    #pragma unroll
    for (int oo = 0; oo < 4; oo++) {
        int o = O0 + og*4 + oo;
        float bv = conv1_b[o];
        float r[8];
        #pragma unroll
        for (int p = 0; p < 4; p++) {
            float lo, hi;
            unpack2(acc2[oo][p], lo, hi);
            r[2*p]   = leaky(lo + bv);
            r[2*p+1] = leaky(hi + bv);
        }
        float4* dst = (float4*)&g_h[(size_t)(b*128 + o)*4096 + S0 + sg*8];
        dst[0] = make_float4(r[0], r[1], r[2], r[3]);
        dst[1] = make_float4(r[4], r[5], r[6], r[7]);
    }
}

// ---------------- K5: 3x3 conv + bias + leaky -> men2rel, fused scores + g (FFMA2) ----------------
// grid (i=64, b=8); block 256 = 16 jg x 16 og; tile 8o x 4j; CC=8
__global__ void k_conv2(const float* __restrict__ conv2_b, float* __restrict__ men,
                        const float* __restrict__ score_w, const int* __restrict__ edge_mat,
                        const float* __restrict__ m_bias) {
    const int CC = 8;
    __shared__ __align__(16) float hs[CC*3*68];
    __shared__ __align__(16) float ws[CC*9*128];
    __shared__ float scr[16*64];
    int tid = threadIdx.x;
    int jg = tid & 15, og = tid >> 4;
    int j0 = jg * 4, o0 = og * 8;
    int i = blockIdx.x, b = blockIdx.y;

    u64t acc2[4][4];   // [o-pair][jj]
    #pragma unroll
    for (int a = 0; a < 4; a++)
        #pragma unroll
        for (int j = 0; j < 4; j++) acc2[a][j] = 0ULL;

    for (int cb = 0; cb < 128; cb += CC) {
        __syncthreads();
        for (int l = tid; l < CC*3*66; l += 256) {
            int c = l / 198, r = l % 198;
            int ky = r / 66, jj = r % 66;
            int gi = i + ky - 1, gj = jj - 1;
            float v = 0.f;
            if (gi >= 0 && gi < 64 && gj >= 0 && gj < 64)
                v = g_h[((size_t)(b*128 + cb + c)*64 + gi)*64 + gj];
            hs[(c*3 + ky)*68 + jj] = v;
        }
        for (int l = tid; l < CC*9*128; l += 256)
            ws[l] = g_w2t[cb*9*128 + l];
        __syncthreads();

        #pragma unroll
        for (int c2 = 0; c2 < CC; c2++) {
            #pragma unroll
            for (int ky = 0; ky < 3; ky++) {
                const float* hr = &hs[(c2*3 + ky)*68 + j0];
                u64t hb[6];
                #pragma unroll
                for (int t = 0; t < 6; t++) hb[t] = pack2(hr[t], hr[t]);
                #pragma unroll
                for (int kx = 0; kx < 3; kx++) {
                    const ulonglong2* wp = (const ulonglong2*)&ws[((c2*3 + ky)*3 + kx)*128 + o0];
                    ulonglong2 wa = wp[0], wb = wp[1];   // 4 o-pairs
                    #pragma unroll
                    for (int jj = 0; jj < 4; jj++) {
                        u64t h2 = hb[jj + kx];
                        ffma2(acc2[0][jj], wa.x, h2);
                        ffma2(acc2[1][jj], wa.y, h2);
                        ffma2(acc2[2][jj], wb.x, h2);
                        ffma2(acc2[3][jj], wb.y, h2);
                    }
                }
            }
        }
    }
    // epilogue: bias+leaky, write men2rel, accumulate score partials
    float part[4] = {0.f, 0.f, 0.f, 0.f};
    #pragma unroll
    for (int p = 0; p < 4; p++) {
        int oE = o0 + 2*p, oO = oE + 1;
        float bvE = conv2_b[oE], bvO = conv2_b[oO];
        float swE = score_w[oE], swO = score_w[oO];
        float rE[4], rO[4];
        #pragma unroll
        for (int jj = 0; jj < 4; jj++) {
            float lo, hi;
            unpack2(acc2[p][jj], lo, hi);
            rE[jj] = leaky(lo + bvE);
            rO[jj] = leaky(hi + bvO);
            part[jj] = fmaf(swE, rE[jj], part[jj]);
            part[jj] = fmaf(swO, rO[jj], part[jj]);
        }
        *(float4*)&men[((size_t)(b*128 + oE)*64 + i)*64 + j0] = make_float4(rE[0], rE[1], rE[2], rE[3]);
        *(float4*)&men[((size_t)(b*128 + oO)*64 + i)*64 + j0] = make_float4(rO[0], rO[1], rO[2], rO[3]);
    }
    #pragma unroll
    for (int jj = 0; jj < 4; jj++) scr[og*64 + j0 + jj] = part[jj];
    __syncthreads();
    if (tid < 64) {
        int j = tid;
        float s = 0.f;
        #pragma unroll
        for (int g = 0; g < 16; g++) s += scr[g*64 + j];
        int idx = b*4096 + i*64 + j;
        g_gmat[idx] = g_logist[idx] + leaky(s) + g_etd[edge_mat[idx]] + m_bias[idx];
    }
}

// ---------------- K7: final softmax-attention + residual ----------------
// dyn smem: Ps[64][68] | PT[64][68] | Yl[64][132] | Xl[64][132]; grid (b=8, i-half=2)
#define LP 132
#define SMEM_FINAL ((2*64*PP + 2*64*LP) * 4)
__global__ void k_final(const float* __restrict__ x, const float* __restrict__ y,
                        float* __restrict__ out_x, float* __restrict__ out_y) {
    extern __shared__ __align__(16) float sm[];
    float* Ps = sm;
    float* PT = Ps + 64*PP;
    float* Yl = PT + 64*PP;
    float* Xl = Yl + 64*LP;
    __shared__ float red[8];
    __shared__ float rinv[64], cinv[64];
    int tid = threadIdx.x, b = blockIdx.x;

    float lm = -1e30f;
    for (int idx = tid; idx < 4096; idx += 256) {
        int m = idx >> 6, n = idx & 63;
        float v = g_gmat[b*4096 + idx];
        Ps[m*PP + n] = v;
        lm = fmaxf(lm, v);
    }
    for (int idx = tid; idx < 8192; idx += 256) {
        int i = idx >> 6, k = idx & 63;
        Yl[k*LP + i] = g_ylin[b*8192 + idx];   // Yl[n][i]
        Xl[k*LP + i] = g_xlin[b*8192 + idx];   // Xl[m][i]
    }
    #pragma unroll
    for (int off = 16; off; off >>= 1) lm = fmaxf(lm, __shfl_xor_sync(0xffffffffu, lm, off));
    if ((tid & 31) == 0) red[tid >> 5] = lm;
    __syncthreads();
    float T = red[0];
    #pragma unroll
    for (int w = 1; w < 8; w++) T = fmaxf(T, red[w]);
    for (int idx = tid; idx < 4096; idx += 256) {
        int m = idx >> 6, n = idx & 63;
        float v = __expf(Ps[m*PP + n] - T);
        Ps[m*PP + n] = v;
        PT[n*PP + m] = v;
    }
    __syncthreads();
    if (tid < 64) {
        float s = 0.f;
        #pragma unroll 8
        for (int n = 0; n < 64; n++) s += PT[n*PP + tid];
        rinv[tid] = 1.f / s;
    } else if (tid < 128) {
        int n = tid - 64;
        float s = 0.f;
        #pragma unroll 8
        for (int m = 0; m < 64; m++) s += Ps[m*PP + n];
        cinv[n] = 1.f / s;
    }
    __syncthreads();

    int mg = tid & 15, ig = tid >> 4;
    int m0 = mg * 4, i0 = blockIdx.y * 64 + ig * 4;

    // out_x[b,i,m] = rinv[m]*sum_n P[m,n]*Ylin[n,i] + x[b,i,m]
    {
        float acc[4][4] = {};
        #pragma unroll 4
        for (int n = 0; n < 64; n++) {
            float4 pv = *(const float4*)&PT[n*PP + m0];
            float4 yv = *(const float4*)&Yl[n*LP + i0];
            float p4[4] = {pv.x, pv.y, pv.z, pv.w};
            float y4[4] = {yv.x, yv.y, yv.z, yv.w};
            #pragma unroll
            for (int mm = 0; mm < 4; mm++)
                #pragma unroll
                for (int ii = 0; ii < 4; ii++)
                    acc[mm][ii] = fmaf(p4[mm], y4[ii], acc[mm][ii]);
        }
        #pragma unroll
        for (int ii = 0; ii < 4; ii++) {
            int i = i0 + ii;
            #pragma unroll
            for (int mm = 0; mm < 4; mm++) {
                int m = m0 + mm;
                out_x[(b*128 + i)*64 + m] = acc[mm][ii]*rinv[m] + x[(b*128 + i)*64 + m];
            }
        }
    }
    // out_y[b,i,n] = cinv[n]*sum_m P[m,n]*Xlin[m,i] + y[b,i,n]
    {
        int n0 = m0;
        float acc[4][4] = {};
        #pragma unroll 4
        for (int m = 0; m < 64; m++) {
            float4 pv = *(const float4*)&Ps[m*PP + n0];
            float4 xv = *(const float4*)&Xl[m*LP + i0];
            float p4[4] = {pv.x, pv.y, pv.z, pv.w};
            float x4[4] = {xv.x, xv.y, xv.z, xv.w};
            #pragma unroll
            for (int nn = 0; nn < 4; nn++)
                #pragma unroll
                for (int ii = 0; ii < 4; ii++)
                    acc[nn][ii] = fmaf(p4[nn], x4[ii], acc[nn][ii]);
        }
        #pragma unroll
        for (int ii = 0; ii < 4; ii++) {
            int i = i0 + ii;
            #pragma unroll
            for (int nn = 0; nn < 4; nn++) {
                int n = n0 + nn;
                out_y[(b*128 + i)*64 + n] = acc[nn][ii]*cinv[n] + y[(b*128 + i)*64 + n];
            }
        }
    }
}

// ---------------- launch ----------------
extern "C" void kernel_launch(void* const* d_in, const int* in_sizes, int n_in,
                              void* d_out, int out_size) {
    const float* x          = (const float*)d_in[0];
    const float* y          = (const float*)d_in[1];
    const float* m_bias     = (const float*)d_in[2];
    const int*   edge_mat   = (const int*)  d_in[3];
    const float* p_bias     = (const float*)d_in[4];
    const int*   path_mat   = (const int*)  d_in[5];
    const float* pre_out    = (const float*)d_in[6];
    const float* xc1_w      = (const float*)d_in[7];
    const float* yc1_w      = (const float*)d_in[8];
    const float* xc2_w      = (const float*)d_in[9];
    const float* xc2_b      = (const float*)d_in[10];
    const float* yc2_w      = (const float*)d_in[11];
    const float* yc2_b      = (const float*)d_in[12];
    const float* pconv_w    = (const float*)d_in[13];
    const float* econv_w    = (const float*)d_in[14];
    const float* conv1_w    = (const float*)d_in[15];
    const float* conv1_b    = (const float*)d_in[16];
    const float* conv2_w    = (const float*)d_in[17];
    const float* conv2_b    = (const float*)d_in[18];
    const float* score_w    = (const float*)d_in[19];
    const float* xlin_w     = (const float*)d_in[20];
    const float* ylin_w     = (const float*)d_in[21];
    const float* edge_table = (const float*)d_in[22];
    const float* path_table = (const float*)d_in[23];

    float* out_x = (float*)d_out;
    float* out_y = out_x + B_*CIN_*E_;
    float* men   = out_y + B_*CIN_*E_;

    cudaFuncSetAttribute(k_path,  cudaFuncAttributeMaxDynamicSharedMemorySize, SMEM_PATH);
    cudaFuncSetAttribute(k_final, cudaFuncAttributeMaxDynamicSharedMemorySize, SMEM_FINAL);

    k_prep<<<64, 256>>>(path_table, pconv_w, edge_table, econv_w, conv1_w, conv2_w);
    k_feat<<<dim3(B_, 2), 256>>>(x, y, xc1_w, yc1_w, xlin_w, ylin_w);
    k_selflog<<<B_, 128>>>(xc2_w, xc2_b, yc2_w, yc2_b);
    k_path<<<B_*E_, 256, SMEM_PATH>>>(p_bias, path_mat);
    k_conv1<<<dim3(32, 2, B_), 256>>>(pre_out, conv1_b);
    k_conv2<<<dim3(64, B_), 256>>>(conv2_b, men, score_w, edge_mat, m_bias);
    k_final<<<dim3(B_, 2), 256, SMEM_FINAL>>>(x, y, out_x, out_y);
}